// round 13
// baseline (speedup 1.0000x reference)
#include <cuda_runtime.h>
#include <math.h>

#define BB 8
#define NN 8192
#define MM 4096
#define HH 128
#define WW 128

#define G    64
#define GC   (G * G)           // 4096 cells per batch
#define TPB  1024
#define PPT  (NN / TPB)        // 8 points per thread
#define QPT  (MM / TPB)        // 4 queries per thread
#define CPT  (GC / TPB)        // 4 cells per thread

#define R      4               // lanes per query
#define QBLK   (TPB / R)       // 256 queries per block
#define GRIDSZ (BB * MM / QBLK)  // 128 blocks -> one co-resident wave

#define PTS_CAP   2048         // staged points cap (32KB)
#define ROWS_CAP  15           // staged row cap -> sstarts <= 15*64+1 = 961

__device__ float    g_mean[BB];
__device__ int      g_starts[BB * (GC + 1)];
__device__ float4   g_pts[BB * NN];
__device__ float4   g_q[BB * MM];
__device__ unsigned g_bar;     // epoch grid barrier (never reset)

__device__ __forceinline__ int cell_of(float v) {
    int c = (int)(v * (float)G);
    return min(max(c, 0), G - 1);
}

__device__ __forceinline__ void scan_counts(int* scnt, int* swscan, int tid,
                                            int lane, int wrp, int* starts) {
    int cnt[CPT], cur[CPT];
    int sum = 0;
    #pragma unroll
    for (int i = 0; i < CPT; ++i) { cnt[i] = scnt[tid * CPT + i]; sum += cnt[i]; }

    int v = sum;
    #pragma unroll
    for (int o = 1; o < 32; o <<= 1) {
        int n = __shfl_up_sync(0xffffffffu, v, o);
        if (lane >= o) v += n;
    }
    if (lane == 31) swscan[wrp] = v;
    __syncthreads();
    if (tid < 32) {
        int w = swscan[tid];
        #pragma unroll
        for (int o = 1; o < 32; o <<= 1) {
            int n = __shfl_up_sync(0xffffffffu, w, o);
            if (tid >= o) w += n;
        }
        swscan[tid] = w;
    }
    __syncthreads();
    int off = v - sum + (wrp ? swscan[wrp - 1] : 0);

    #pragma unroll
    for (int i = 0; i < CPT; ++i) {
        if (starts) starts[tid * CPT + i] = off;
        cur[i] = off;
        off += cnt[i];
    }
    __syncthreads();
    #pragma unroll
    for (int i = 0; i < CPT; ++i) scnt[tid * CPT + i] = cur[i];
    __syncthreads();
}

// candidate update (identical FP sequence everywhere)
__device__ __forceinline__ void upd(const float2 p, float4 c, float& best, int& bidx) {
    float dx = p.x - c.x;
    float dy = p.y - c.y;
    float d2 = __fadd_rn(__fmul_rn(dx, dx), __fmul_rn(dy, dy));
    int   idx = __float_as_int(c.w);
    if (d2 < best || (d2 == best && idx < bidx)) { best = d2; bidx = idx; }
}

// global window scan (fallback / expansion outside cache)
__device__ __forceinline__ void scan_window_g(
    const float2 p, const int* __restrict__ starts, const float4* __restrict__ pts,
    int ilo, int ihi, int jlo, int jhi, int sub, float& best, int& bidx)
{
    for (int i = ilo; i <= ihi; ++i) {
        int s = starts[i * G + jlo];
        int e = starts[i * G + jhi + 1];
        for (int k = s + sub; k < e; k += R)
            upd(p, pts[k], best, bidx);
    }
}

// smem window scan (rows must be within [rlo..rhi])
__device__ __forceinline__ void scan_window_s(
    const float2 p, const int* sstarts, const float4* spts, int rlo, int ps,
    int ilo, int ihi, int jlo, int jhi, int sub, float& best, int& bidx)
{
    for (int i = ilo; i <= ihi; ++i) {
        int rbase = (i - rlo) * G;
        int s = sstarts[rbase + jlo];
        int e = sstarts[rbase + jhi + 1];
        for (int k = s + sub; k < e; k += R)
            upd(p, spts[k - ps], best, bidx);
    }
}

__device__ __forceinline__ void mergeR(float& best, int& bidx) {
    #pragma unroll
    for (int o = 1; o < R; o <<= 1) {
        float od2 = __shfl_xor_sync(0xffffffffu, best, o);
        int   oid = __shfl_xor_sync(0xffffffffu, bidx, o);
        if (od2 < best || (od2 == best && oid < bidx)) { best = od2; bidx = oid; }
    }
}

// ---------------- fused: build + grid barrier + smem-staged query ----------------
__global__ void __launch_bounds__(TPB) fused_kernel(
    const float* __restrict__ xc_off,
    const float* __restrict__ yc_off,
    const float* __restrict__ yc_on,
    const float* __restrict__ xt,
    const float* __restrict__ logit,
    float* __restrict__ out)
{
    const int tid  = threadIdx.x;
    const int lane = tid & 31, wrp = tid >> 5;

    // shared: build-phase histogram aliases query-phase staging buffers
    __shared__ __align__(16) unsigned char s_raw[PTS_CAP * 16 + (ROWS_CAP * G + 4) * 4];
    int*    scnt    = (int*)s_raw;                    // build phase (16KB)
    float4* spts    = (float4*)s_raw;                 // query phase
    int*    sstarts = (int*)(s_raw + PTS_CAP * 16);   // query phase
    __shared__ int   swscan[32];
    __shared__ int   s_rowmin, s_rowmax, s_ps, s_npts;

    // ================= phase 1: build (first 16 blocks) =================
    if (blockIdx.x < BB * 2) {
        const int b    = blockIdx.x >> 1;
        const int role = blockIdx.x & 1;

        #pragma unroll
        for (int i = 0; i < CPT; ++i) scnt[tid + i * TPB] = 0;

        if (role == 0) {
            float2 pt[PPT];
            int    pc[PPT], rk[PPT];
            const float2* cpts = (const float2*)(xc_off + (size_t)b * NN * 2);
            #pragma unroll
            for (int k = 0; k < PPT; ++k) {
                pt[k] = cpts[tid + k * TPB];
                pc[k] = cell_of(pt[k].x) * G + cell_of(pt[k].y);
            }
            __syncthreads();
            #pragma unroll
            for (int k = 0; k < PPT; ++k) rk[k] = atomicAdd(&scnt[pc[k]], 1);
            __syncthreads();

            scan_counts(scnt, swscan, tid, lane, wrp, g_starts + b * (GC + 1));
            if (tid == 0) g_starts[b * (GC + 1) + GC] = NN;

            float4* dst = g_pts + (size_t)b * NN;
            #pragma unroll
            for (int k = 0; k < PPT; ++k) {
                int pos = scnt[pc[k]] + rk[k];
                dst[pos] = make_float4(pt[k].x, pt[k].y, 0.f, __int_as_float(tid + k * TPB));
            }
        } else {
            __shared__ float swsum[32];
            {
                const float* p = yc_on + (size_t)b * HH * WW;
                float s = 0.f;
                #pragma unroll
                for (int k = 0; k < (HH * WW) / TPB; ++k) s += p[tid + k * TPB];
                #pragma unroll
                for (int o = 16; o; o >>= 1) s += __shfl_down_sync(0xffffffffu, s, o);
                if (lane == 0) swsum[wrp] = s;
            }

            float2 qt[QPT];
            int    qc[QPT], rk[QPT];
            const float2* q = (const float2*)(xt + (size_t)b * MM * 2);
            #pragma unroll
            for (int k = 0; k < QPT; ++k) {
                qt[k] = q[tid + k * TPB];
                qc[k] = cell_of(qt[k].x) * G + cell_of(qt[k].y);
            }
            __syncthreads();
            if (tid < 32) {
                float s = swsum[tid];
                #pragma unroll
                for (int o = 16; o; o >>= 1) s += __shfl_down_sync(0xffffffffu, s, o);
                if (tid == 0) g_mean[b] = s * (1.0f / (HH * WW));
            }
            #pragma unroll
            for (int k = 0; k < QPT; ++k) rk[k] = atomicAdd(&scnt[qc[k]], 1);
            __syncthreads();

            scan_counts(scnt, swscan, tid, lane, wrp, (int*)0);

            float4* dst = g_q + (size_t)b * MM;
            #pragma unroll
            for (int k = 0; k < QPT; ++k) {
                int pos = scnt[qc[k]] + rk[k];
                dst[pos] = make_float4(qt[k].x, qt[k].y, 0.f, __int_as_float(tid + k * TPB));
            }
        }
    }

    // ================= grid barrier (epoch-based, replay-safe) =================
    __threadfence();
    __syncthreads();
    if (tid == 0) {
        unsigned v = atomicAdd(&g_bar, 1u);
        unsigned tgt = (v / GRIDSZ + 1u) * GRIDSZ;
        while (*((volatile unsigned*)&g_bar) < tgt) { }
        s_rowmin = G; s_rowmax = -1;   // init staging reduction while we're here
    }
    __syncthreads();
    __threadfence();

    // ================= phase 2: query (all blocks, smem-staged) =================
    const int qbase = blockIdx.x * QBLK;          // sorted-query base of this block
    const int t     = qbase + (tid >> 2);         // this group's query
    const int sub   = tid & (R - 1);
    const int b     = t / MM;

    const float4 q = g_q[t];
    const float2 p = make_float2(q.x, q.y);
    const int    m = __float_as_int(q.w);

    const int*    starts = g_starts + b * (GC + 1);
    const float4* pts    = g_pts + (size_t)b * NN;

    const int qcx = cell_of(p.x);
    const int qcy = cell_of(p.y);

    // ---- block row-range + staging ----
    if (sub == 0) {
        atomicMin(&s_rowmin, qcx);
        atomicMax(&s_rowmax, qcx);
    }
    __syncthreads();
    const int rlo = max(s_rowmin - 1, 0);
    const int rhi = min(s_rowmax + 1, G - 1);
    const int nrows_c = rhi - rlo + 1;
    if (tid == 0) {
        int ps = starts[rlo * G];
        int pe = starts[(rhi + 1) * G];
        s_ps = ps; s_npts = pe - ps;
    }
    __syncthreads();
    const int ps = s_ps, npts = s_npts;
    const bool cached = (nrows_c <= ROWS_CAP) && (npts <= PTS_CAP);
    if (cached) {
        for (int k = tid; k < npts; k += TPB) spts[k] = pts[ps + k];
        const int nst = nrows_c * G + 1;
        for (int k = tid; k < nst; k += TPB) sstarts[k] = starts[rlo * G + k];
    }
    __syncthreads();

    // ---- bilinear: 4 corner loads spread over lanes 0..3 ----
    float x = p.x, y = p.y;
    float fx = x * 127.0f;
    float fy = y * 127.0f;
    int ix = (int)floorf(fx);
    int iy = (int)floorf(fy);
    ix = min(max(ix, 0), 126);
    iy = min(max(iy, 0), 126);

    float vcorner;
    {
        int di = (sub >> 1) & 1;
        int dj = sub & 1;
        vcorner = yc_on[((size_t)b * HH + ix + di) * WW + (iy + dj)];
    }
    const int gbase = lane & ~(R - 1);
    float v00 = __shfl_sync(0xffffffffu, vcorner, gbase + 0);
    float v01 = __shfl_sync(0xffffffffu, vcorner, gbase + 1);
    float v10 = __shfl_sync(0xffffffffu, vcorner, gbase + 2);
    float v11 = __shfl_sync(0xffffffffu, vcorner, gbase + 3);

    float best = 3.402823466e+38f;
    int   bidx = 0x7fffffff;

    // ---- initial 3x3 window ----
    int ilo = max(qcx - 1, 0), ihi = min(qcx + 1, G - 1);
    int jlo = max(qcy - 1, 0), jhi = min(qcy + 1, G - 1);
    if (cached) {
        // rows qcx±1 are within [rlo..rhi] by construction
        const int nr = ihi - ilo + 1;
        int s0, e0, s1 = 0, e1 = 0, s2 = 0, e2 = 0;
        int rb0 = (ilo - rlo) * G;
        s0 = sstarts[rb0 + jlo];       e0 = sstarts[rb0 + jhi + 1];
        if (nr > 1) { s1 = sstarts[rb0 + G + jlo];     e1 = sstarts[rb0 + G + jhi + 1]; }
        if (nr > 2) { s2 = sstarts[rb0 + 2*G + jlo];   e2 = sstarts[rb0 + 2*G + jhi + 1]; }
        const int l0 = e0 - s0, l1 = e1 - s1, l2 = e2 - s2;
        const int total = l0 + l1 + l2;
        for (int g = sub; g < total; g += R) {
            int k, g2 = g;
            if (g2 < l0)            k = s0 + g2;
            else { g2 -= l0;
                if (g2 < l1)        k = s1 + g2;
                else                k = s2 + (g2 - l1); }
            upd(p, spts[k - ps], best, bidx);
        }
    } else {
        scan_window_g(p, starts, pts, ilo, ihi, jlo, jhi, sub, best, bidx);
    }
    mergeR(best, bidx);

    // (essentially never) ensure at least one candidate
    while (bidx == 0x7fffffff) {
        ilo = max(ilo - 1, 0); ihi = min(ihi + 1, G - 1);
        jlo = max(jlo - 1, 0); jhi = min(jhi + 1, G - 1);
        scan_window_g(p, starts, pts, ilo, ihi, jlo, jhi, sub, best, bidx);
        mergeR(best, bidx);
        if (ilo == 0 && ihi == G - 1 && jlo == 0 && jhi == G - 1) break;
    }

    // ---- disk-cover certificate (round-up sqrt + eps -> exact) ----
    for (;;) {
        float rad = __fsqrt_ru(best);
        int nilo = max((int)floorf((p.x - rad) * (float)G - 1e-3f), 0);
        int nihi = min((int)floorf((p.x + rad) * (float)G + 1e-3f), G - 1);
        int njlo = max((int)floorf((p.y - rad) * (float)G - 1e-3f), 0);
        int njhi = min((int)floorf((p.y + rad) * (float)G + 1e-3f), G - 1);
        if (nilo >= ilo && nihi <= ihi && njlo >= jlo && njhi <= jhi) break;
        ilo = min(ilo, nilo); ihi = max(ihi, nihi);
        jlo = min(jlo, njlo); jhi = max(jhi, njhi);
        if (cached && ilo >= rlo && ihi <= rhi)
            scan_window_s(p, sstarts, spts, rlo, ps, ilo, ihi, jlo, jhi, sub, best, bidx);
        else
            scan_window_g(p, starts, pts, ilo, ihi, jlo, jhi, sub, best, bidx);
        mergeR(best, bidx);
    }

    if (sub == 0) {
        bool oob = (x < 0.0f) || (x > 1.0f) || (y < 0.0f) || (y > 1.0f);
        float wx = fx - (float)ix;
        float wy = fy - (float)iy;
        float yt_on = (1.0f - wx) * (1.0f - wy) * v00
                    + (1.0f - wx) * wy          * v01
                    + wx          * (1.0f - wy) * v10
                    + wx          * wy          * v11;
        if (oob) yt_on = g_mean[b];

        float yt_off = yc_off[(size_t)b * NN + bidx];
        float lg  = logit[0];
        float mix = 1.0f / (1.0f + expf(-lg));
        out[(size_t)b * MM + m] = mix * yt_off + (1.0f - mix) * yt_on;
    }
}

extern "C" void kernel_launch(void* const* d_in, const int* in_sizes, int n_in,
                              void* d_out, int out_size) {
    const float* xc_off = (const float*)d_in[0];
    const float* yc_off = (const float*)d_in[1];
    const float* yc_on  = (const float*)d_in[3];
    const float* xt     = (const float*)d_in[4];
    const float* logit  = (const float*)d_in[5];
    float* out = (float*)d_out;

    fused_kernel<<<GRIDSZ, TPB>>>(xc_off, yc_off, yc_on, xt, logit, out);
}

// round 14
// speedup vs baseline: 1.0976x; 1.0976x over previous
#include <cuda_runtime.h>
#include <math.h>

#define BB 8
#define NN 8192
#define MM 4096
#define HH 128
#define WW 128

#define G    64
#define GC   (G * G)            // 4096 cells per batch
#define TPB  1024
#define CPT  (GC / TPB)         // 4 cells per thread (scan blocks)

#define R      4                // lanes per query
#define GRIDSZ 128              // one co-resident wave (128 <= 148 SMs)

#define NPTS_T (BB * NN)        // 65536
#define NQ_T   (BB * MM)        // 32768

__device__ float    g_mean[BB];
__device__ float    g_part[GRIDSZ];
__device__ int      g_cnt[BB * GC];      // static-zeroed; re-zeroed each launch in P2
__device__ int      g_qcnt[BB * GC];
__device__ int      g_starts[BB * (GC + 1)];
__device__ int      g_qst[BB * GC];
__device__ float4   g_pts[BB * NN];
__device__ float4   g_q[BB * MM];
__device__ unsigned g_bar;               // epoch grid barrier (never reset)

__device__ __forceinline__ int cell_of(float v) {
    int c = (int)(v * (float)G);
    return min(max(c, 0), G - 1);
}

__device__ __forceinline__ void grid_bar(int tid) {
    __threadfence();
    __syncthreads();
    __shared__ unsigned s_tgt;
    if (tid == 0) {
        unsigned v = atomicAdd(&g_bar, 1u);
        unsigned tgt = (v / GRIDSZ + 1u) * GRIDSZ;
        while (*((volatile unsigned*)&g_bar) < tgt) { }
        s_tgt = tgt;
    }
    __syncthreads();
    __threadfence();
    (void)s_tgt;
}

// exclusive scan of 4096 counts (smem) -> writes offsets to `starts`
__device__ __forceinline__ void scan_counts(int* scnt, int* swscan, int tid,
                                            int lane, int wrp, int* starts) {
    int cnt[CPT];
    int sum = 0;
    #pragma unroll
    for (int i = 0; i < CPT; ++i) { cnt[i] = scnt[tid * CPT + i]; sum += cnt[i]; }

    int v = sum;
    #pragma unroll
    for (int o = 1; o < 32; o <<= 1) {
        int n = __shfl_up_sync(0xffffffffu, v, o);
        if (lane >= o) v += n;
    }
    if (lane == 31) swscan[wrp] = v;
    __syncthreads();
    if (tid < 32) {
        int w = swscan[tid];
        #pragma unroll
        for (int o = 1; o < 32; o <<= 1) {
            int n = __shfl_up_sync(0xffffffffu, w, o);
            if (tid >= o) w += n;
        }
        swscan[tid] = w;
    }
    __syncthreads();
    int off = v - sum + (wrp ? swscan[wrp - 1] : 0);

    #pragma unroll
    for (int i = 0; i < CPT; ++i) {
        starts[tid * CPT + i] = off;
        off += cnt[i];
    }
}

__device__ __forceinline__ void upd(const float2 p, float4 c, float& best, int& bidx) {
    float dx = p.x - c.x;
    float dy = p.y - c.y;
    float d2 = __fadd_rn(__fmul_rn(dx, dx), __fmul_rn(dy, dy));
    int   idx = __float_as_int(c.w);
    if (d2 < best || (d2 == best && idx < bidx)) { best = d2; bidx = idx; }
}

__device__ __forceinline__ void scan_window_g(
    const float2 p, const int* __restrict__ starts, const float4* __restrict__ pts,
    int ilo, int ihi, int jlo, int jhi, int sub, float& best, int& bidx)
{
    for (int i = ilo; i <= ihi; ++i) {
        int s = starts[i * G + jlo];
        int e = starts[i * G + jhi + 1];
        for (int k = s + sub; k < e; k += R)
            upd(p, pts[k], best, bidx);
    }
}

__device__ __forceinline__ void mergeR(float& best, int& bidx) {
    #pragma unroll
    for (int o = 1; o < R; o <<= 1) {
        float od2 = __shfl_xor_sync(0xffffffffu, best, o);
        int   oid = __shfl_xor_sync(0xffffffffu, bidx, o);
        if (od2 < best || (od2 == best && oid < bidx)) { best = od2; bidx = oid; }
    }
}

// ------------- fused: distributed build (3 grid barriers) + query -------------
__global__ void __launch_bounds__(TPB) fused_kernel(
    const float* __restrict__ xc_off,
    const float* __restrict__ yc_off,
    const float* __restrict__ yc_on,
    const float* __restrict__ xt,
    const float* __restrict__ logit,
    float* __restrict__ out)
{
    const int tid  = threadIdx.x;
    const int lane = tid & 31, wrp = tid >> 5;
    const int gt   = blockIdx.x * TPB + tid;

    __shared__ int   scnt[GC];
    __shared__ int   swscan[32];
    __shared__ float swsum[32];

    // ================= phase 1: histogram + yc_on partial sums =================
    // one element per thread; counts arrays are zero (static init / previous
    // launch's phase-2 re-zero), so the atomic return IS the in-cell rank.
    float2 pt = make_float2(0.f, 0.f), qt = make_float2(0.f, 0.f);
    int pb = 0, pcell = 0, prank = 0, pn = 0;
    int qb = 0, qcell = 0, qrank = 0, qm = 0;
    bool isPt = (gt < NPTS_T);
    bool isQ  = !isPt && (gt < NPTS_T + NQ_T);

    if (isPt) {
        pb = gt >> 13;                    // / NN
        pn = gt & (NN - 1);
        pt = ((const float2*)xc_off)[gt];
        pcell = cell_of(pt.x) * G + cell_of(pt.y);
        prank = atomicAdd(&g_cnt[pb * GC + pcell], 1);
    } else if (isQ) {
        int g2 = gt - NPTS_T;
        qb = g2 >> 12;                    // / MM
        qm = g2 & (MM - 1);
        qt = ((const float2*)xt)[g2];
        qcell = cell_of(qt.x) * G + cell_of(qt.y);
        qrank = atomicAdd(&g_qcnt[qb * GC + qcell], 1);
    }

    // yc_on block partial (gt spans exactly BB*HH*WW = 131072)
    {
        float s = yc_on[gt];
        #pragma unroll
        for (int o = 16; o; o >>= 1) s += __shfl_down_sync(0xffffffffu, s, o);
        if (lane == 0) swsum[wrp] = s;
        __syncthreads();
        if (tid < 32) {
            float s2 = swsum[tid];
            #pragma unroll
            for (int o = 16; o; o >>= 1) s2 += __shfl_down_sync(0xffffffffu, s2, o);
            if (tid == 0) g_part[blockIdx.x] = s2;
        }
    }

    grid_bar(tid);

    // ================= phase 2: scans + mean (24 blocks) =================
    if (blockIdx.x < BB) {
        const int b = blockIdx.x;
        #pragma unroll
        for (int i = 0; i < CPT; ++i) scnt[tid * CPT + i] = g_cnt[b * GC + tid * CPT + i];
        scan_counts(scnt, swscan, tid, lane, wrp, g_starts + b * (GC + 1));
        if (tid == 0) g_starts[b * (GC + 1) + GC] = NN;
        #pragma unroll
        for (int i = 0; i < CPT; ++i) g_cnt[b * GC + tid * CPT + i] = 0;  // for next launch
    } else if (blockIdx.x < BB * 2) {
        const int b = blockIdx.x - BB;
        #pragma unroll
        for (int i = 0; i < CPT; ++i) scnt[tid * CPT + i] = g_qcnt[b * GC + tid * CPT + i];
        scan_counts(scnt, swscan, tid, lane, wrp, g_qst + b * GC);
        #pragma unroll
        for (int i = 0; i < CPT; ++i) g_qcnt[b * GC + tid * CPT + i] = 0;
    } else if (blockIdx.x < BB * 3) {
        const int b = blockIdx.x - BB * 2;
        if (tid == 0) {
            float s = 0.f;
            #pragma unroll
            for (int k = 0; k < GRIDSZ / BB; ++k) s += g_part[b * (GRIDSZ / BB) + k];  // fixed order
            g_mean[b] = s * (1.0f / (HH * WW));
        }
    }

    grid_bar(tid);

    // ================= phase 3: scatter =================
    if (isPt) {
        int pos = g_starts[pb * (GC + 1) + pcell] + prank;
        g_pts[pb * NN + pos] = make_float4(pt.x, pt.y, 0.f, __int_as_float(pn));
    } else if (isQ) {
        int pos = g_qst[qb * GC + qcell] + qrank;
        g_q[qb * MM + pos] = make_float4(qt.x, qt.y, 0.f, __int_as_float(qm));
    }

    grid_bar(tid);

    // ================= phase 4: query =================
    const int t   = gt / R;
    const int sub = gt & (R - 1);
    const int b   = t / MM;

    const float4 q = g_q[t];
    const float2 p = make_float2(q.x, q.y);
    const int    m = __float_as_int(q.w);

    const int*    starts = g_starts + b * (GC + 1);
    const float4* pts    = g_pts + (size_t)b * NN;

    // bilinear: 4 corner loads spread over lanes 0..3 of the group
    float x = p.x, y = p.y;
    float fx = x * 127.0f;
    float fy = y * 127.0f;
    int ix = (int)floorf(fx);
    int iy = (int)floorf(fy);
    ix = min(max(ix, 0), 126);
    iy = min(max(iy, 0), 126);

    float vcorner;
    {
        int di = (sub >> 1) & 1;
        int dj = sub & 1;
        vcorner = yc_on[((size_t)b * HH + ix + di) * WW + (iy + dj)];
    }
    const int gbase = lane & ~(R - 1);
    float v00 = __shfl_sync(0xffffffffu, vcorner, gbase + 0);
    float v01 = __shfl_sync(0xffffffffu, vcorner, gbase + 1);
    float v10 = __shfl_sync(0xffffffffu, vcorner, gbase + 2);
    float v11 = __shfl_sync(0xffffffffu, vcorner, gbase + 3);

    const int qcx = cell_of(p.x);
    const int qcy = cell_of(p.y);

    float best = 3.402823466e+38f;
    int   bidx = 0x7fffffff;

    // initial 3x3 window: hoist row bounds, flatten segments, lane-stride
    int ilo = max(qcx - 1, 0), ihi = min(qcx + 1, G - 1);
    int jlo = max(qcy - 1, 0), jhi = min(qcy + 1, G - 1);
    {
        const int nrows = ihi - ilo + 1;
        int s0, e0, s1 = 0, e1 = 0, s2 = 0, e2 = 0;
        s0 = starts[ilo * G + jlo];
        e0 = starts[ilo * G + jhi + 1];
        if (nrows > 1) { s1 = starts[(ilo + 1) * G + jlo]; e1 = starts[(ilo + 1) * G + jhi + 1]; }
        if (nrows > 2) { s2 = starts[(ilo + 2) * G + jlo]; e2 = starts[(ilo + 2) * G + jhi + 1]; }
        const int l0 = e0 - s0, l1 = e1 - s1, l2 = e2 - s2;
        const int total = l0 + l1 + l2;

        for (int g = sub; g < total; g += R) {
            int k, g2 = g;
            if (g2 < l0)            k = s0 + g2;
            else { g2 -= l0;
                if (g2 < l1)        k = s1 + g2;
                else                k = s2 + (g2 - l1); }
            upd(p, pts[k], best, bidx);
        }
    }
    mergeR(best, bidx);

    // (essentially never) ensure at least one candidate
    while (bidx == 0x7fffffff) {
        ilo = max(ilo - 1, 0); ihi = min(ihi + 1, G - 1);
        jlo = max(jlo - 1, 0); jhi = min(jhi + 1, G - 1);
        scan_window_g(p, starts, pts, ilo, ihi, jlo, jhi, sub, best, bidx);
        mergeR(best, bidx);
        if (ilo == 0 && ihi == G - 1 && jlo == 0 && jhi == G - 1) break;
    }

    // disk-cover certificate (round-up sqrt + eps -> exact)
    for (;;) {
        float rad = __fsqrt_ru(best);
        int nilo = max((int)floorf((p.x - rad) * (float)G - 1e-3f), 0);
        int nihi = min((int)floorf((p.x + rad) * (float)G + 1e-3f), G - 1);
        int njlo = max((int)floorf((p.y - rad) * (float)G - 1e-3f), 0);
        int njhi = min((int)floorf((p.y + rad) * (float)G + 1e-3f), G - 1);
        if (nilo >= ilo && nihi <= ihi && njlo >= jlo && njhi <= jhi) break;
        ilo = min(ilo, nilo); ihi = max(ihi, nihi);
        jlo = min(jlo, njlo); jhi = max(jhi, njhi);
        scan_window_g(p, starts, pts, ilo, ihi, jlo, jhi, sub, best, bidx);  // idempotent
        mergeR(best, bidx);
    }

    if (sub == 0) {
        bool oob = (x < 0.0f) || (x > 1.0f) || (y < 0.0f) || (y > 1.0f);
        float wx = fx - (float)ix;
        float wy = fy - (float)iy;
        float yt_on = (1.0f - wx) * (1.0f - wy) * v00
                    + (1.0f - wx) * wy          * v01
                    + wx          * (1.0f - wy) * v10
                    + wx          * wy          * v11;
        if (oob) yt_on = g_mean[b];

        float yt_off = yc_off[(size_t)b * NN + bidx];
        float lg  = logit[0];
        float mix = 1.0f / (1.0f + expf(-lg));
        out[(size_t)b * MM + m] = mix * yt_off + (1.0f - mix) * yt_on;
    }
}

extern "C" void kernel_launch(void* const* d_in, const int* in_sizes, int n_in,
                              void* d_out, int out_size) {
    const float* xc_off = (const float*)d_in[0];
    const float* yc_off = (const float*)d_in[1];
    const float* yc_on  = (const float*)d_in[3];
    const float* xt     = (const float*)d_in[4];
    const float* logit  = (const float*)d_in[5];
    float* out = (float*)d_out;

    fused_kernel<<<GRIDSZ, TPB>>>(xc_off, yc_off, yc_on, xt, logit, out);
}